// round 15
// baseline (speedup 1.0000x reference)
#include <cuda_runtime.h>
#include <math.h>
#include <stdint.h>

#define BB 8
#define CC 64
#define LL 2048
#define MM 1024
#define GG 4
#define CPG 16
#define HH 8
#define EE 8
#define EPSV 1e-5f

__device__ __forceinline__ float ex2f(float x) {
    float r;
    asm("ex2.approx.f32 %0, %1;" : "=f"(r) : "f"(x));
    return r;
}
__device__ __forceinline__ uint32_t tf32r(float x) {
    uint32_t u;
    asm("cvt.rna.tf32.f32 %0, %1;" : "=r"(u) : "f"(x));
    return u;
}
// D = A*B + C  (m16n8k8 tf32)
__device__ __forceinline__ void mma8(float& d0, float& d1, float& d2, float& d3,
                                     uint32_t a0, uint32_t a1, uint32_t a2, uint32_t a3,
                                     uint32_t b0, uint32_t b1,
                                     float c0, float c1, float c2, float c3) {
    asm volatile(
        "mma.sync.aligned.m16n8k8.row.col.f32.tf32.tf32.f32 "
        "{%0,%1,%2,%3},{%4,%5,%6,%7},{%8,%9},{%10,%11,%12,%13};"
        : "=f"(d0), "=f"(d1), "=f"(d2), "=f"(d3)
        : "r"(a0), "r"(a1), "r"(a2), "r"(a3), "r"(b0), "r"(b1),
          "f"(c0), "f"(c1), "f"(c2), "f"(c3));
}
// D += A*B
__device__ __forceinline__ void mma8acc(float& d0, float& d1, float& d2, float& d3,
                                        uint32_t a0, uint32_t a1, uint32_t a2, uint32_t a3,
                                        uint32_t b0, uint32_t b1) {
    asm volatile(
        "mma.sync.aligned.m16n8k8.row.col.f32.tf32.tf32.f32 "
        "{%0,%1,%2,%3},{%4,%5,%6,%7},{%8,%9},{%0,%1,%2,%3};"
        : "+f"(d0), "+f"(d1), "+f"(d2), "+f"(d3)
        : "r"(a0), "r"(a1), "r"(a2), "r"(a3), "r"(b0), "r"(b1));
}

// ---------------- scratch ----------------
__device__ float g_xat[BB*CC*LL];
__device__ float g_qp [BB*CC*LL];
__device__ float g_xa [BB*CC*MM];
__device__ float g_v  [BB*CC*MM];
__device__ float g_v1 [BB*CC*MM];
__device__ float g_out[BB*CC*LL];
__device__ float g_xs [BB*CC*LL];
__device__ float g_xs2[BB*CC*LL];
__device__ float g_s1d[CC];
__device__ float g_s2d[CC];
__device__ float g_s1f[CC];
__device__ float g_s2f[CC];

// ---------------- K1: q conv -> sigmoid gate -> x_atten -> q_ conv ----------------
__global__ void __launch_bounds__(256) k1_gate(const float* __restrict__ x,
                                               const float* __restrict__ qw,
                                               const float* __restrict__ kw) {
    __shared__ float qws[CPG*CPG], kws[CPG*CPG];
    int t = threadIdx.x;
    int g = blockIdx.y;
    if (blockIdx.x == 0 && g == 0 && t < CC) {
        g_s1d[t] = 0.f; g_s2d[t] = 0.f; g_s1f[t] = 0.f; g_s2f[t] = 0.f;
    }
    if (t < CPG*CPG) {
        qws[t] = qw[(size_t)g*CPG*CPG + t];
        kws[t] = kw[(size_t)g*CPG*CPG + t];
    }
    __syncthreads();
    int gl = blockIdx.x * 256 + t;
    int b = gl >> 11, l = gl & (LL-1);
    size_t base = (size_t)b*CC*LL + l + (size_t)g*CPG*LL;
    float xv[CPG], xa[CPG];
    #pragma unroll
    for (int i = 0; i < CPG; i++) xv[i] = x[base + (size_t)i*LL];
    #pragma unroll
    for (int c = 0; c < CPG; c++) {
        float s = 0.f;
        #pragma unroll
        for (int i = 0; i < CPG; i++) s = fmaf(qws[c*CPG+i], xv[i], s);
        xa[c] = xv[c] / (1.f + __expf(-s));
    }
    #pragma unroll
    for (int i = 0; i < CPG; i++) g_xat[base + (size_t)i*LL] = xa[i];
    #pragma unroll
    for (int c = 0; c < CPG; c++) {
        float s = 0.f;
        #pragma unroll
        for (int i = 0; i < CPG; i++) s = fmaf(kws[c*CPG+i], xa[i], s);
        g_qp[base + (size_t)c*LL] = s;
    }
}

// ---------------- K2: odd/even shuffle + down conv + BN stats ----------------
#define TM2 32
__global__ void __launch_bounds__(256) k2_down(const float* __restrict__ dw) {
    __shared__ float xt[CC][2*TM2 + 4];
    int t = threadIdx.x;
    int m0 = blockIdx.x * TM2, b = blockIdx.y;
    int l0 = 2*m0 - 2;
    const int W = 2*TM2 + 4;
    for (int idx = t; idx < CC*W; idx += 256) {
        int i = idx / W, s = idx % W;
        int l = l0 + s;
        xt[i][s] = (l >= 0 && l < LL) ? g_xat[((size_t)b*CC + i)*LL + l] : 0.f;
    }
    __syncthreads();
    int o = t >> 2, qq = t & 3;
    float acc[8];
    #pragma unroll
    for (int j = 0; j < 8; j++) acc[j] = 0.f;
    const float* wb = dw + (size_t)o*CC*3;
    int sb = 2*(qq*8) + ((o < 32) ? 1 : 0);
    for (int i = 0; i < CC; i++) {
        float w0 = __ldg(wb + i*3 + 0), w1 = __ldg(wb + i*3 + 1), w2 = __ldg(wb + i*3 + 2);
        const float* row = xt[i];
        float a0 = row[sb], a1 = row[sb+2];
        #pragma unroll
        for (int j = 0; j < 8; j++) {
            float a2 = row[sb + 4 + 2*j];
            acc[j] = fmaf(w0, a0, fmaf(w1, a1, fmaf(w2, a2, acc[j])));
            a0 = a1; a1 = a2;
        }
    }
    float s1 = 0.f, s2 = 0.f;
    size_t base = ((size_t)b*CC + o)*MM + m0 + qq*8;
    #pragma unroll
    for (int j = 0; j < 8; j++) { float v = acc[j]; g_xa[base + j] = v; s1 += v; s2 = fmaf(v, v, s2); }
    s1 += __shfl_xor_sync(0xffffffffu, s1, 1); s2 += __shfl_xor_sync(0xffffffffu, s2, 1);
    s1 += __shfl_xor_sync(0xffffffffu, s1, 2); s2 += __shfl_xor_sync(0xffffffffu, s2, 2);
    if (qq == 0) { atomicAdd(&g_s1d[o], s1); atomicAdd(&g_s2d[o], s2); }
}

// ---------------- K3: BN + ReLU + v/v1 pointwise grouped convs ----------------
__global__ void __launch_bounds__(256) k3_vconv(const float* __restrict__ vw,
                                                const float* __restrict__ v1w,
                                                const float* __restrict__ dgam,
                                                const float* __restrict__ dbet) {
    __shared__ float sc[CPG], sh[CPG], vws[CPG*CPG], v1ws[CPG*CPG];
    int t = threadIdx.x;
    int g = blockIdx.y;
    if (t < CPG) {
        int c = g*CPG + t;
        const float invn = 1.f / (float)(BB*MM);
        float mean = g_s1d[c] * invn;
        float var  = g_s2d[c] * invn - mean*mean;
        float s = dgam[c] * rsqrtf(var + EPSV);
        sc[t] = s; sh[t] = dbet[c] - mean*s;
    }
    if (t < CPG*CPG) {
        vws[t]  = vw [(size_t)g*CPG*CPG + t];
        v1ws[t] = v1w[(size_t)g*CPG*CPG + t];
    }
    __syncthreads();
    int gl = blockIdx.x * 256 + t;
    int b = gl >> 10, m = gl & (MM-1);
    size_t base = (size_t)b*CC*MM + m + (size_t)g*CPG*MM;
    float xr[CPG];
    #pragma unroll
    for (int i = 0; i < CPG; i++)
        xr[i] = fmaxf(0.f, fmaf(g_xa[base + (size_t)i*MM], sc[i], sh[i]));
    #pragma unroll
    for (int c = 0; c < CPG; c++) {
        float s = 0.f, s1 = 0.f;
        #pragma unroll
        for (int i = 0; i < CPG; i++) {
            s  = fmaf(vws [c*CPG+i], xr[i], s);
            s1 = fmaf(v1ws[c*CPG+i], xr[i], s1);
        }
        g_v [base + (size_t)c*MM] = s;
        g_v1[base + (size_t)c*MM] = s1;
    }
}

// ---------------- K4: mma.sync tf32 flash attention, intra-block m-split ----------------
// l-tile 256, 512 threads: warps 0-7 do m-chunks [0,64), warps 8-15 do [64,128)
// over the SAME rows; partials combined in smem (KB region reused). Grid 8x64=512
// blocks -> 3 blocks/SM co-resident.
#define NCH (MM/8)        // 128 chunks
#define HCH (NCH/2)       // 64 per half
#define PSTR 13           // padded partial stride (floats)
#define K4M_SMEM (2*NCH*32*8 + 64)   // 65536 + colsum

__global__ void __launch_bounds__(512, 3) k4_mma() {
    extern __shared__ float2 sm4[];
    float2* KB = sm4;                      // [NCH*32]
    float2* VB = sm4 + NCH*32;             // [NCH*32]
    float* scv = (float*)(sm4 + 2*NCH*32); // [8] V column sums
    float* part = (float*)sm4;             // overlay on KB after mainloop (13KB used)
    int t = threadIdx.x;
    int bh = blockIdx.y;
    size_t vb = (size_t)bh * EE * MM;      // b*CC + h*8 == 8*bh
    const float SCL = 0.35355339059327373f * 1.4426950408889634f;  // 1/sqrt(E)*log2(e)

    for (int i = t; i < NCH*32; i += 512) {
        int lane = i & 31, chunk = i >> 5;
        int j = lane & 3, g = lane >> 2;
        int m = chunk*8 + g;
        float k0 = g_v[vb + (size_t)(2*j  )*MM + m] * SCL;
        float k1 = g_v[vb + (size_t)(2*j+1)*MM + m] * SCL;
        float2 kk; kk.x = __uint_as_float(tf32r(k0)); kk.y = __uint_as_float(tf32r(k1));
        KB[i] = kk;
        float2 vv = *(const float2*)(g_v1 + vb + (size_t)g*MM + chunk*8 + 2*j);
        float2 vt; vt.x = __uint_as_float(tf32r(vv.x)); vt.y = __uint_as_float(tf32r(vv.y));
        VB[i] = vt;
    }
    // V column sums (exact fp32): warps 0..7 sum row (wid)
    {
        int lane = t & 31, wid = t >> 5;
        if (wid < EE) {
            float s = 0.f;
            const float* vr = g_v1 + vb + (size_t)wid*MM;
            for (int m = lane; m < MM; m += 32) s += vr[m];
            #pragma unroll
            for (int o = 16; o; o >>= 1) s += __shfl_xor_sync(0xffffffffu, s, o);
            if (lane == 0) scv[wid] = s;
        }
    }
    __syncthreads();

    int lane = t & 31, wid = t >> 5;
    int half = wid >> 3, wr = wid & 7;
    int j = lane & 3, g = lane >> 2;
    int lr = blockIdx.x*256 + wr*32 + g;    // frag A rows: lr, lr+8; B: lr+16, lr+24
    size_t qbase = (size_t)(8*bh)*LL;

    size_t q0 = qbase + (size_t)(2*j)*LL + lr;
    size_t q1 = qbase + (size_t)(2*j+1)*LL + lr;
    uint32_t qa0 = tf32r(g_qp[q0]),      qa1 = tf32r(g_qp[q1]);
    uint32_t qa2 = tf32r(g_qp[q0 + 8]),  qa3 = tf32r(g_qp[q1 + 8]);
    uint32_t qb0 = tf32r(g_qp[q0 + 16]), qb1 = tf32r(g_qp[q1 + 16]);
    uint32_t qb2 = tf32r(g_qp[q0 + 24]), qb3 = tf32r(g_qp[q1 + 24]);

    float dA0 = 0.f, dA1 = 0.f, dA2 = 0.f, dA3 = 0.f;
    float dB0 = 0.f, dB1 = 0.f, dB2 = 0.f, dB3 = 0.f;
    float denA0 = 0.f, denA1 = 0.f, denB0 = 0.f, denB1 = 0.f;
    const float2* kb = KB + lane + half*HCH*32;
    const float2* vp = VB + lane + half*HCH*32;
    const float zf = 0.f;

    #pragma unroll 2
    for (int c = 0; c < HCH; c++) {
        float2 kk = kb[c*32];
        float2 vv = vp[c*32];
        uint32_t bk0 = __float_as_uint(kk.x), bk1 = __float_as_uint(kk.y);
        float sA0, sA1, sA2, sA3, sB0, sB1, sB2, sB3;
        mma8(sA0, sA1, sA2, sA3, qa0, qa1, qa2, qa3, bk0, bk1, zf, zf, zf, zf);
        mma8(sB0, sB1, sB2, sB3, qb0, qb1, qb2, qb3, bk0, bk1, zf, zf, zf, zf);
        float pA0 = ex2f(sA0) - 1.f;
        float pA1 = ex2f(sA1) - 1.f;
        float pA2 = ex2f(sA2) - 1.f;
        float pA3 = ex2f(sA3) - 1.f;
        float pB0 = ex2f(sB0) - 1.f;
        float pB1 = ex2f(sB1) - 1.f;
        float pB2 = ex2f(sB2) - 1.f;
        float pB3 = ex2f(sB3) - 1.f;
        denA0 += pA0 + pA1; denA1 += pA2 + pA3;
        denB0 += pB0 + pB1; denB1 += pB2 + pB3;
        uint32_t bv0 = __float_as_uint(vv.x), bv1 = __float_as_uint(vv.y);
        mma8acc(dA0, dA1, dA2, dA3,
                __float_as_uint(pA0), __float_as_uint(pA1),
                __float_as_uint(pA2), __float_as_uint(pA3), bv0, bv1);
        mma8acc(dB0, dB1, dB2, dB3,
                __float_as_uint(pB0), __float_as_uint(pB1),
                __float_as_uint(pB2), __float_as_uint(pB3), bv0, bv1);
    }

    // intra-block combine: upper half stores partials, lower half adds
    __syncthreads();            // all reads of KB/VB done; safe to overlay
    if (half == 1) {
        float* pp = part + (t - 256) * PSTR;
        pp[0] = dA0; pp[1] = dA1; pp[2] = dA2;  pp[3] = dA3;
        pp[4] = dB0; pp[5] = dB1; pp[6] = dB2;  pp[7] = dB3;
        pp[8] = denA0 + denA1;   // fold two den pairs? no — keep separate:
        pp[8] = denA0; pp[9] = denA1; pp[10] = denB0; pp[11] = denB1;
    }
    __syncthreads();
    if (half == 0) {
        const float* pp = part + t * PSTR;
        dA0 += pp[0]; dA1 += pp[1]; dA2 += pp[2];  dA3 += pp[3];
        dB0 += pp[4]; dB1 += pp[5]; dB2 += pp[6];  dB3 += pp[7];
        denA0 += pp[8]; denA1 += pp[9]; denB0 += pp[10]; denB1 += pp[11];

        // reduce denominators across the 4-thread quad
        denA0 += __shfl_xor_sync(0xffffffffu, denA0, 1);
        denA0 += __shfl_xor_sync(0xffffffffu, denA0, 2);
        denA1 += __shfl_xor_sync(0xffffffffu, denA1, 1);
        denA1 += __shfl_xor_sync(0xffffffffu, denA1, 2);
        denB0 += __shfl_xor_sync(0xffffffffu, denB0, 1);
        denB0 += __shfl_xor_sync(0xffffffffu, denB0, 2);
        denB1 += __shfl_xor_sync(0xffffffffu, denB1, 1);
        denB1 += __shfl_xor_sync(0xffffffffu, denB1, 2);
        float iA0 = 1.f / ((float)MM + denA0);
        float iA1 = 1.f / ((float)MM + denA1);
        float iB0 = 1.f / ((float)MM + denB0);
        float iB1 = 1.f / ((float)MM + denB1);

        float cs0 = scv[2*j], cs1 = scv[2*j+1];
        size_t iA = qbase + (size_t)(2*j)*LL + lr;
        size_t iB = iA + LL;
        float o;
        o = (cs0 + dA0)*iA0; g_out[iA     ] = o; g_xs[iA     ] = o + g_xat[iA     ];
        o = (cs1 + dA1)*iA0; g_out[iB     ] = o; g_xs[iB     ] = o + g_xat[iB     ];
        o = (cs0 + dA2)*iA1; g_out[iA +  8] = o; g_xs[iA +  8] = o + g_xat[iA +  8];
        o = (cs1 + dA3)*iA1; g_out[iB +  8] = o; g_xs[iB +  8] = o + g_xat[iB +  8];
        o = (cs0 + dB0)*iB0; g_out[iA + 16] = o; g_xs[iA + 16] = o + g_xat[iA + 16];
        o = (cs1 + dB1)*iB0; g_out[iB + 16] = o; g_xs[iB + 16] = o + g_xat[iB + 16];
        o = (cs0 + dB2)*iB1; g_out[iA + 24] = o; g_xs[iA + 24] = o + g_xat[iA + 24];
        o = (cs1 + dB3)*iB1; g_out[iB + 24] = o; g_xs[iB + 24] = o + g_xat[iB + 24];
    }
}

// ---------------- K5: out conv (K=3, groups=4 over concat(xs,q_,out)) + residual + stats ----------------
#define TL5 128
__global__ void __launch_bounds__(256) k5_outconv(const float* __restrict__ ow) {
    __shared__ float xcs[48][TL5 + 2];
    int t = threadIdx.x;
    int l0 = blockIdx.x * TL5, g = blockIdx.y, b = blockIdx.z;
    const int W = TL5 + 2;
    for (int idx = t; idx < 48*W; idx += 256) {
        int j = idx / W, s = idx % W;
        int l = l0 - 1 + s;
        int u = g*48 + j;
        float val = 0.f;
        if (l >= 0 && l < LL) {
            const float* src; int ch;
            if      (u < 64)  { src = g_xs;  ch = u; }
            else if (u < 128) { src = g_qp;  ch = u - 64; }
            else              { src = g_out; ch = u - 128; }
            val = src[((size_t)b*CC + ch)*LL + l];
        }
        xcs[j][s] = val;
    }
    __syncthreads();
    int cl = t >> 4, sub = t & 15;
    int c = g*CPG + cl;
    int lbase = sub * 8;
    float acc[8];
    #pragma unroll
    for (int jj = 0; jj < 8; jj++) acc[jj] = 0.f;
    const float* wb = ow + (size_t)c*48*3;
    for (int j = 0; j < 48; j++) {
        float w0 = __ldg(wb + j*3 + 0), w1 = __ldg(wb + j*3 + 1), w2 = __ldg(wb + j*3 + 2);
        const float* row = xcs[j];
        float a0 = row[lbase], a1 = row[lbase+1];
        #pragma unroll
        for (int jj = 0; jj < 8; jj++) {
            float a2 = row[lbase + 2 + jj];
            acc[jj] = fmaf(w0, a0, fmaf(w1, a1, fmaf(w2, a2, acc[jj])));
            a0 = a1; a1 = a2;
        }
    }
    float s1 = 0.f, s2 = 0.f;
    size_t base = ((size_t)b*CC + c)*LL + l0 + lbase;
    #pragma unroll
    for (int jj = 0; jj < 8; jj++) {
        float v = acc[jj] + g_xs[base + jj];
        g_xs2[base + jj] = v;
        s1 += v; s2 = fmaf(v, v, s2);
    }
    #pragma unroll
    for (int k = 1; k < 16; k <<= 1) {
        s1 += __shfl_xor_sync(0xffffffffu, s1, k);
        s2 += __shfl_xor_sync(0xffffffffu, s2, k);
    }
    if (sub == 0) { atomicAdd(&g_s1f[c], s1); atomicAdd(&g_s2f[c], s2); }
}

// ---------------- K6: final BN + ReLU -> output ----------------
__global__ void __launch_bounds__(256) k6_final(const float* __restrict__ gam,
                                                const float* __restrict__ bet,
                                                float* __restrict__ out) {
    int idx = blockIdx.x * 256 + threadIdx.x;
    int c = (idx >> 11) & (CC-1);
    const float invn = 1.f / (float)(BB*LL);
    float mean = g_s1f[c] * invn;
    float var  = g_s2f[c] * invn - mean*mean;
    float s  = gam[c] * rsqrtf(var + EPSV);
    float shv = bet[c] - mean*s;
    out[idx] = fmaxf(0.f, fmaf(g_xs2[idx], s, shv));
}

// ---------------- launch ----------------
extern "C" void kernel_launch(void* const* d_in, const int* in_sizes, int n_in,
                              void* d_out, int out_size) {
    const float* x   = (const float*)d_in[0];
    const float* qw  = (const float*)d_in[1];
    const float* kw  = (const float*)d_in[2];
    const float* vw  = (const float*)d_in[3];
    const float* v1w = (const float*)d_in[4];
    const float* ow  = (const float*)d_in[5];
    const float* dw  = (const float*)d_in[6];
    const float* dg  = (const float*)d_in[7];
    const float* db  = (const float*)d_in[8];
    const float* gam = (const float*)d_in[9];
    const float* bet = (const float*)d_in[10];
    float* out = (float*)d_out;

    static int configured = 0;
    if (!configured) {
        cudaFuncSetAttribute(k4_mma, cudaFuncAttributeMaxDynamicSharedMemorySize, K4M_SMEM);
        configured = 1;
    }

    k1_gate<<<dim3((BB*LL)/256, GG), 256>>>(x, qw, kw);
    k2_down<<<dim3(MM/TM2, BB), 256>>>(dw);
    k3_vconv<<<dim3((BB*MM)/256, GG), 256>>>(vw, v1w, dg, db);
    k4_mma<<<dim3(LL/256, BB*HH), 512, K4M_SMEM>>>();
    k5_outconv<<<dim3(LL/TL5, GG, BB), 256>>>(ow);
    k6_final<<<(BB*CC*LL)/256, 256>>>(gam, bet, out);
}

// round 16
// speedup vs baseline: 1.0151x; 1.0151x over previous
#include <cuda_runtime.h>
#include <math.h>
#include <stdint.h>

#define BB 8
#define CC 64
#define LL 2048
#define MM 1024
#define GG 4
#define CPG 16
#define HH 8
#define EE 8
#define EPSV 1e-5f

__device__ __forceinline__ float ex2f(float x) {
    float r;
    asm("ex2.approx.f32 %0, %1;" : "=f"(r) : "f"(x));
    return r;
}
__device__ __forceinline__ uint32_t tf32r(float x) {
    uint32_t u;
    asm("cvt.rna.tf32.f32 %0, %1;" : "=r"(u) : "f"(x));
    return u;
}
// 2^s - 1 via degree-4 Taylor (|s| <~ 0.3 => err < 3e-6). Runs on fma pipe.
#define PA1 0.6931471805599453f
#define PA2 0.2402265069591007f
#define PA3 0.0555041086648216f
#define PA4 0.0096181291076285f
__device__ __forceinline__ float exp2m1(float s) {
    float h = fmaf(s, PA4, PA3);
    h = fmaf(s, h, PA2);
    h = fmaf(s, h, PA1);
    return s * h;
}
// D = A*B + C  (m16n8k8 tf32)
__device__ __forceinline__ void mma8(float& d0, float& d1, float& d2, float& d3,
                                     uint32_t a0, uint32_t a1, uint32_t a2, uint32_t a3,
                                     uint32_t b0, uint32_t b1,
                                     float c0, float c1, float c2, float c3) {
    asm volatile(
        "mma.sync.aligned.m16n8k8.row.col.f32.tf32.tf32.f32 "
        "{%0,%1,%2,%3},{%4,%5,%6,%7},{%8,%9},{%10,%11,%12,%13};"
        : "=f"(d0), "=f"(d1), "=f"(d2), "=f"(d3)
        : "r"(a0), "r"(a1), "r"(a2), "r"(a3), "r"(b0), "r"(b1),
          "f"(c0), "f"(c1), "f"(c2), "f"(c3));
}
// D += A*B
__device__ __forceinline__ void mma8acc(float& d0, float& d1, float& d2, float& d3,
                                        uint32_t a0, uint32_t a1, uint32_t a2, uint32_t a3,
                                        uint32_t b0, uint32_t b1) {
    asm volatile(
        "mma.sync.aligned.m16n8k8.row.col.f32.tf32.tf32.f32 "
        "{%0,%1,%2,%3},{%4,%5,%6,%7},{%8,%9},{%0,%1,%2,%3};"
        : "+f"(d0), "+f"(d1), "+f"(d2), "+f"(d3)
        : "r"(a0), "r"(a1), "r"(a2), "r"(a3), "r"(b0), "r"(b1));
}

// ---------------- scratch ----------------
__device__ float g_xat[BB*CC*LL];
__device__ float g_qp [BB*CC*LL];
__device__ float g_xa [BB*CC*MM];
__device__ float g_v  [BB*CC*MM];
__device__ float g_v1 [BB*CC*MM];
__device__ float g_out[BB*CC*LL];
__device__ float g_xs [BB*CC*LL];
__device__ float g_xs2[BB*CC*LL];
__device__ float g_s1d[CC];
__device__ float g_s2d[CC];
__device__ float g_s1f[CC];
__device__ float g_s2f[CC];

// ---------------- K1: q conv -> sigmoid gate -> x_atten -> q_ conv ----------------
__global__ void __launch_bounds__(256) k1_gate(const float* __restrict__ x,
                                               const float* __restrict__ qw,
                                               const float* __restrict__ kw) {
    __shared__ float qws[CPG*CPG], kws[CPG*CPG];
    int t = threadIdx.x;
    int g = blockIdx.y;
    if (blockIdx.x == 0 && g == 0 && t < CC) {
        g_s1d[t] = 0.f; g_s2d[t] = 0.f; g_s1f[t] = 0.f; g_s2f[t] = 0.f;
    }
    if (t < CPG*CPG) {
        qws[t] = qw[(size_t)g*CPG*CPG + t];
        kws[t] = kw[(size_t)g*CPG*CPG + t];
    }
    __syncthreads();
    int gl = blockIdx.x * 256 + t;
    int b = gl >> 11, l = gl & (LL-1);
    size_t base = (size_t)b*CC*LL + l + (size_t)g*CPG*LL;
    float xv[CPG], xa[CPG];
    #pragma unroll
    for (int i = 0; i < CPG; i++) xv[i] = x[base + (size_t)i*LL];
    #pragma unroll
    for (int c = 0; c < CPG; c++) {
        float s = 0.f;
        #pragma unroll
        for (int i = 0; i < CPG; i++) s = fmaf(qws[c*CPG+i], xv[i], s);
        xa[c] = xv[c] / (1.f + __expf(-s));
    }
    #pragma unroll
    for (int i = 0; i < CPG; i++) g_xat[base + (size_t)i*LL] = xa[i];
    #pragma unroll
    for (int c = 0; c < CPG; c++) {
        float s = 0.f;
        #pragma unroll
        for (int i = 0; i < CPG; i++) s = fmaf(kws[c*CPG+i], xa[i], s);
        g_qp[base + (size_t)c*LL] = s;
    }
}

// ---------------- K2: odd/even shuffle + down conv + BN stats ----------------
#define TM2 32
__global__ void __launch_bounds__(256) k2_down(const float* __restrict__ dw) {
    __shared__ float xt[CC][2*TM2 + 4];
    int t = threadIdx.x;
    int m0 = blockIdx.x * TM2, b = blockIdx.y;
    int l0 = 2*m0 - 2;
    const int W = 2*TM2 + 4;
    for (int idx = t; idx < CC*W; idx += 256) {
        int i = idx / W, s = idx % W;
        int l = l0 + s;
        xt[i][s] = (l >= 0 && l < LL) ? g_xat[((size_t)b*CC + i)*LL + l] : 0.f;
    }
    __syncthreads();
    int o = t >> 2, qq = t & 3;
    float acc[8];
    #pragma unroll
    for (int j = 0; j < 8; j++) acc[j] = 0.f;
    const float* wb = dw + (size_t)o*CC*3;
    int sb = 2*(qq*8) + ((o < 32) ? 1 : 0);
    for (int i = 0; i < CC; i++) {
        float w0 = __ldg(wb + i*3 + 0), w1 = __ldg(wb + i*3 + 1), w2 = __ldg(wb + i*3 + 2);
        const float* row = xt[i];
        float a0 = row[sb], a1 = row[sb+2];
        #pragma unroll
        for (int j = 0; j < 8; j++) {
            float a2 = row[sb + 4 + 2*j];
            acc[j] = fmaf(w0, a0, fmaf(w1, a1, fmaf(w2, a2, acc[j])));
            a0 = a1; a1 = a2;
        }
    }
    float s1 = 0.f, s2 = 0.f;
    size_t base = ((size_t)b*CC + o)*MM + m0 + qq*8;
    #pragma unroll
    for (int j = 0; j < 8; j++) { float v = acc[j]; g_xa[base + j] = v; s1 += v; s2 = fmaf(v, v, s2); }
    s1 += __shfl_xor_sync(0xffffffffu, s1, 1); s2 += __shfl_xor_sync(0xffffffffu, s2, 1);
    s1 += __shfl_xor_sync(0xffffffffu, s1, 2); s2 += __shfl_xor_sync(0xffffffffu, s2, 2);
    if (qq == 0) { atomicAdd(&g_s1d[o], s1); atomicAdd(&g_s2d[o], s2); }
}

// ---------------- K3: BN + ReLU + v/v1 pointwise grouped convs ----------------
__global__ void __launch_bounds__(256) k3_vconv(const float* __restrict__ vw,
                                                const float* __restrict__ v1w,
                                                const float* __restrict__ dgam,
                                                const float* __restrict__ dbet) {
    __shared__ float sc[CPG], sh[CPG], vws[CPG*CPG], v1ws[CPG*CPG];
    int t = threadIdx.x;
    int g = blockIdx.y;
    if (t < CPG) {
        int c = g*CPG + t;
        const float invn = 1.f / (float)(BB*MM);
        float mean = g_s1d[c] * invn;
        float var  = g_s2d[c] * invn - mean*mean;
        float s = dgam[c] * rsqrtf(var + EPSV);
        sc[t] = s; sh[t] = dbet[c] - mean*s;
    }
    if (t < CPG*CPG) {
        vws[t]  = vw [(size_t)g*CPG*CPG + t];
        v1ws[t] = v1w[(size_t)g*CPG*CPG + t];
    }
    __syncthreads();
    int gl = blockIdx.x * 256 + t;
    int b = gl >> 10, m = gl & (MM-1);
    size_t base = (size_t)b*CC*MM + m + (size_t)g*CPG*MM;
    float xr[CPG];
    #pragma unroll
    for (int i = 0; i < CPG; i++)
        xr[i] = fmaxf(0.f, fmaf(g_xa[base + (size_t)i*MM], sc[i], sh[i]));
    #pragma unroll
    for (int c = 0; c < CPG; c++) {
        float s = 0.f, s1 = 0.f;
        #pragma unroll
        for (int i = 0; i < CPG; i++) {
            s  = fmaf(vws [c*CPG+i], xr[i], s);
            s1 = fmaf(v1ws[c*CPG+i], xr[i], s1);
        }
        g_v [base + (size_t)c*MM] = s;
        g_v1[base + (size_t)c*MM] = s1;
    }
}

// ---------------- K4: mma.sync tf32 flash attention, 2 frags/warp, 512 threads ----------------
// R14 config (best) + exp pipe-balance: 6 of 8 exps on MUFU (ex2), 2 on fma pipe
// (degree-4 poly of 2^s-1). MUFU per-iter demand 64 -> 48 cyc; fma 32 -> 44 cyc.
#define NCH (MM/8)        // 128 chunks
#define K4M_SMEM (2*NCH*32*8 + 64)   // 65536 + colsum

__global__ void __launch_bounds__(512, 3) k4_mma() {
    extern __shared__ float2 sm4[];
    float2* KB = sm4;                      // [NCH*32]
    float2* VB = sm4 + NCH*32;             // [NCH*32]
    float* scv = (float*)(sm4 + 2*NCH*32); // [8] V column sums
    int t = threadIdx.x;
    int bh = blockIdx.y;
    size_t vb = (size_t)bh * EE * MM;      // b*CC + h*8 == 8*bh
    const float SCL = 0.35355339059327373f * 1.4426950408889634f;  // 1/sqrt(E)*log2(e)

    for (int i = t; i < NCH*32; i += 512) {
        int lane = i & 31, chunk = i >> 5;
        int j = lane & 3, g = lane >> 2;
        int m = chunk*8 + g;
        float k0 = g_v[vb + (size_t)(2*j  )*MM + m] * SCL;
        float k1 = g_v[vb + (size_t)(2*j+1)*MM + m] * SCL;
        float2 kk; kk.x = __uint_as_float(tf32r(k0)); kk.y = __uint_as_float(tf32r(k1));
        KB[i] = kk;
        float2 vv = *(const float2*)(g_v1 + vb + (size_t)g*MM + chunk*8 + 2*j);
        float2 vt; vt.x = __uint_as_float(tf32r(vv.x)); vt.y = __uint_as_float(tf32r(vv.y));
        VB[i] = vt;
    }
    // V column sums (exact fp32): warps 0..7 sum row (wid)
    {
        int lane = t & 31, wid = t >> 5;
        if (wid < EE) {
            float s = 0.f;
            const float* vr = g_v1 + vb + (size_t)wid*MM;
            for (int m = lane; m < MM; m += 32) s += vr[m];
            #pragma unroll
            for (int o = 16; o; o >>= 1) s += __shfl_xor_sync(0xffffffffu, s, o);
            if (lane == 0) scv[wid] = s;
        }
    }
    __syncthreads();

    int lane = t & 31, wid = t >> 5;
    int j = lane & 3, g = lane >> 2;
    int lr = blockIdx.x*512 + wid*32 + g;   // fragment A rows: lr, lr+8; B: lr+16, lr+24
    size_t qbase = (size_t)(8*bh)*LL;

    size_t q0 = qbase + (size_t)(2*j)*LL + lr;
    size_t q1 = qbase + (size_t)(2*j+1)*LL + lr;
    uint32_t qa0 = tf32r(g_qp[q0]),      qa1 = tf32r(g_qp[q1]);
    uint32_t qa2 = tf32r(g_qp[q0 + 8]),  qa3 = tf32r(g_qp[q1 + 8]);
    uint32_t qb0 = tf32r(g_qp[q0 + 16]), qb1 = tf32r(g_qp[q1 + 16]);
    uint32_t qb2 = tf32r(g_qp[q0 + 24]), qb3 = tf32r(g_qp[q1 + 24]);

    float dA0 = 0.f, dA1 = 0.f, dA2 = 0.f, dA3 = 0.f;
    float dB0 = 0.f, dB1 = 0.f, dB2 = 0.f, dB3 = 0.f;
    float denA0 = 0.f, denA1 = 0.f, denB0 = 0.f, denB1 = 0.f;
    const float2* kb = KB + lane;
    const float2* vp = VB + lane;
    const float zf = 0.f;

    #pragma unroll 2
    for (int c = 0; c < NCH; c++) {
        float2 kk = kb[c*32];
        float2 vv = vp[c*32];
        uint32_t bk0 = __float_as_uint(kk.x), bk1 = __float_as_uint(kk.y);
        float sA0, sA1, sA2, sA3, sB0, sB1, sB2, sB3;
        mma8(sA0, sA1, sA2, sA3, qa0, qa1, qa2, qa3, bk0, bk1, zf, zf, zf, zf);
        mma8(sB0, sB1, sB2, sB3, qb0, qb1, qb2, qb3, bk0, bk1, zf, zf, zf, zf);
        // 6 exps on MUFU, 2 on fma pipe (poly) to balance per-pipe demand
        float pA0 = ex2f(sA0) - 1.f;
        float pA1 = ex2f(sA1) - 1.f;
        float pA2 = ex2f(sA2) - 1.f;
        float pA3 = ex2f(sA3) - 1.f;
        float pB0 = ex2f(sB0) - 1.f;
        float pB1 = ex2f(sB1) - 1.f;
        float pB2 = exp2m1(sB2);
        float pB3 = exp2m1(sB3);
        denA0 += pA0 + pA1; denA1 += pA2 + pA3;
        denB0 += pB0 + pB1; denB1 += pB2 + pB3;
        uint32_t bv0 = __float_as_uint(vv.x), bv1 = __float_as_uint(vv.y);
        mma8acc(dA0, dA1, dA2, dA3,
                __float_as_uint(pA0), __float_as_uint(pA1),
                __float_as_uint(pA2), __float_as_uint(pA3), bv0, bv1);
        mma8acc(dB0, dB1, dB2, dB3,
                __float_as_uint(pB0), __float_as_uint(pB1),
                __float_as_uint(pB2), __float_as_uint(pB3), bv0, bv1);
    }

    // reduce denominators across the 4-thread quad
    denA0 += __shfl_xor_sync(0xffffffffu, denA0, 1);
    denA0 += __shfl_xor_sync(0xffffffffu, denA0, 2);
    denA1 += __shfl_xor_sync(0xffffffffu, denA1, 1);
    denA1 += __shfl_xor_sync(0xffffffffu, denA1, 2);
    denB0 += __shfl_xor_sync(0xffffffffu, denB0, 1);
    denB0 += __shfl_xor_sync(0xffffffffu, denB0, 2);
    denB1 += __shfl_xor_sync(0xffffffffu, denB1, 1);
    denB1 += __shfl_xor_sync(0xffffffffu, denB1, 2);
    float iA0 = 1.f / ((float)MM + denA0);
    float iA1 = 1.f / ((float)MM + denA1);
    float iB0 = 1.f / ((float)MM + denB0);
    float iB1 = 1.f / ((float)MM + denB1);

    float cs0 = scv[2*j], cs1 = scv[2*j+1];
    size_t iA = qbase + (size_t)(2*j)*LL + lr;
    size_t iB = iA + LL;
    float o;
    o = (cs0 + dA0)*iA0; g_out[iA     ] = o; g_xs[iA     ] = o + g_xat[iA     ];
    o = (cs1 + dA1)*iA0; g_out[iB     ] = o; g_xs[iB     ] = o + g_xat[iB     ];
    o = (cs0 + dA2)*iA1; g_out[iA +  8] = o; g_xs[iA +  8] = o + g_xat[iA +  8];
    o = (cs1 + dA3)*iA1; g_out[iB +  8] = o; g_xs[iB +  8] = o + g_xat[iB +  8];
    o = (cs0 + dB0)*iB0; g_out[iA + 16] = o; g_xs[iA + 16] = o + g_xat[iA + 16];
    o = (cs1 + dB1)*iB0; g_out[iB + 16] = o; g_xs[iB + 16] = o + g_xat[iB + 16];
    o = (cs0 + dB2)*iB1; g_out[iA + 24] = o; g_xs[iA + 24] = o + g_xat[iA + 24];
    o = (cs1 + dB3)*iB1; g_out[iB + 24] = o; g_xs[iB + 24] = o + g_xat[iB + 24];
}

// ---------------- K5: out conv (K=3, groups=4 over concat(xs,q_,out)) + residual + stats ----------------
#define TL5 128
__global__ void __launch_bounds__(256) k5_outconv(const float* __restrict__ ow) {
    __shared__ float xcs[48][TL5 + 2];
    int t = threadIdx.x;
    int l0 = blockIdx.x * TL5, g = blockIdx.y, b = blockIdx.z;
    const int W = TL5 + 2;
    for (int idx = t; idx < 48*W; idx += 256) {
        int j = idx / W, s = idx % W;
        int l = l0 - 1 + s;
        int u = g*48 + j;
        float val = 0.f;
        if (l >= 0 && l < LL) {
            const float* src; int ch;
            if      (u < 64)  { src = g_xs;  ch = u; }
            else if (u < 128) { src = g_qp;  ch = u - 64; }
            else              { src = g_out; ch = u - 128; }
            val = src[((size_t)b*CC + ch)*LL + l];
        }
        xcs[j][s] = val;
    }
    __syncthreads();
    int cl = t >> 4, sub = t & 15;
    int c = g*CPG + cl;
    int lbase = sub * 8;
    float acc[8];
    #pragma unroll
    for (int jj = 0; jj < 8; jj++) acc[jj] = 0.f;
    const float* wb = ow + (size_t)c*48*3;
    for (int j = 0; j < 48; j++) {
        float w0 = __ldg(wb + j*3 + 0), w1 = __ldg(wb + j*3 + 1), w2 = __ldg(wb + j*3 + 2);
        const float* row = xcs[j];
        float a0 = row[lbase], a1 = row[lbase+1];
        #pragma unroll
        for (int jj = 0; jj < 8; jj++) {
            float a2 = row[lbase + 2 + jj];
            acc[jj] = fmaf(w0, a0, fmaf(w1, a1, fmaf(w2, a2, acc[jj])));
            a0 = a1; a1 = a2;
        }
    }
    float s1 = 0.f, s2 = 0.f;
    size_t base = ((size_t)b*CC + c)*LL + l0 + lbase;
    #pragma unroll
    for (int jj = 0; jj < 8; jj++) {
        float v = acc[jj] + g_xs[base + jj];
        g_xs2[base + jj] = v;
        s1 += v; s2 = fmaf(v, v, s2);
    }
    #pragma unroll
    for (int k = 1; k < 16; k <<= 1) {
        s1 += __shfl_xor_sync(0xffffffffu, s1, k);
        s2 += __shfl_xor_sync(0xffffffffu, s2, k);
    }
    if (sub == 0) { atomicAdd(&g_s1f[c], s1); atomicAdd(&g_s2f[c], s2); }
}

// ---------------- K6: final BN + ReLU -> output ----------------
__global__ void __launch_bounds__(256) k6_final(const float* __restrict__ gam,
                                                const float* __restrict__ bet,
                                                float* __restrict__ out) {
    int idx = blockIdx.x * 256 + threadIdx.x;
    int c = (idx >> 11) & (CC-1);
    const float invn = 1.f / (float)(BB*LL);
    float mean = g_s1f[c] * invn;
    float var  = g_s2f[c] * invn - mean*mean;
    float s  = gam[c] * rsqrtf(var + EPSV);
    float shv = bet[c] - mean*s;
    out[idx] = fmaxf(0.f, fmaf(g_xs2[idx], s, shv));
}

// ---------------- launch ----------------
extern "C" void kernel_launch(void* const* d_in, const int* in_sizes, int n_in,
                              void* d_out, int out_size) {
    const float* x   = (const float*)d_in[0];
    const float* qw  = (const float*)d_in[1];
    const float* kw  = (const float*)d_in[2];
    const float* vw  = (const float*)d_in[3];
    const float* v1w = (const float*)d_in[4];
    const float* ow  = (const float*)d_in[5];
    const float* dw  = (const float*)d_in[6];
    const float* dg  = (const float*)d_in[7];
    const float* db  = (const float*)d_in[8];
    const float* gam = (const float*)d_in[9];
    const float* bet = (const float*)d_in[10];
    float* out = (float*)d_out;

    static int configured = 0;
    if (!configured) {
        cudaFuncSetAttribute(k4_mma, cudaFuncAttributeMaxDynamicSharedMemorySize, K4M_SMEM);
        configured = 1;
    }

    k1_gate<<<dim3((BB*LL)/256, GG), 256>>>(x, qw, kw);
    k2_down<<<dim3(MM/TM2, BB), 256>>>(dw);
    k3_vconv<<<dim3((BB*MM)/256, GG), 256>>>(vw, v1w, dg, db);
    k4_mma<<<dim3(LL/512, BB*HH), 512, K4M_SMEM>>>();
    k5_outconv<<<dim3(LL/TL5, GG, BB), 256>>>(ow);
    k6_final<<<(BB*CC*LL)/256, 256>>>(gam, bet, out);
}

// round 17
// speedup vs baseline: 1.1395x; 1.1226x over previous
#include <cuda_runtime.h>
#include <math.h>
#include <stdint.h>

#define BB 8
#define CC 64
#define LL 2048
#define MM 1024
#define GG 4
#define CPG 16
#define HH 8
#define EE 8
#define EPSV 1e-5f

__device__ __forceinline__ float ex2f(float x) {
    float r;
    asm("ex2.approx.f32 %0, %1;" : "=f"(r) : "f"(x));
    return r;
}
__device__ __forceinline__ uint32_t tf32r(float x) {
    uint32_t u;
    asm("cvt.rna.tf32.f32 %0, %1;" : "=r"(u) : "f"(x));
    return u;
}
// D = A*B + C  (m16n8k8 tf32)
__device__ __forceinline__ void mma8(float& d0, float& d1, float& d2, float& d3,
                                     uint32_t a0, uint32_t a1, uint32_t a2, uint32_t a3,
                                     uint32_t b0, uint32_t b1,
                                     float c0, float c1, float c2, float c3) {
    asm volatile(
        "mma.sync.aligned.m16n8k8.row.col.f32.tf32.tf32.f32 "
        "{%0,%1,%2,%3},{%4,%5,%6,%7},{%8,%9},{%10,%11,%12,%13};"
        : "=f"(d0), "=f"(d1), "=f"(d2), "=f"(d3)
        : "r"(a0), "r"(a1), "r"(a2), "r"(a3), "r"(b0), "r"(b1),
          "f"(c0), "f"(c1), "f"(c2), "f"(c3));
}
// D += A*B
__device__ __forceinline__ void mma8acc(float& d0, float& d1, float& d2, float& d3,
                                        uint32_t a0, uint32_t a1, uint32_t a2, uint32_t a3,
                                        uint32_t b0, uint32_t b1) {
    asm volatile(
        "mma.sync.aligned.m16n8k8.row.col.f32.tf32.tf32.f32 "
        "{%0,%1,%2,%3},{%4,%5,%6,%7},{%8,%9},{%0,%1,%2,%3};"
        : "+f"(d0), "+f"(d1), "+f"(d2), "+f"(d3)
        : "r"(a0), "r"(a1), "r"(a2), "r"(a3), "r"(b0), "r"(b1));
}

// ---------------- scratch ----------------
__device__ float g_xat[BB*CC*LL];
__device__ float g_qp [BB*CC*LL];
__device__ float g_xa [BB*CC*MM];
__device__ float g_v  [BB*CC*MM];
__device__ float g_v1 [BB*CC*MM];
__device__ float g_out[BB*CC*LL];
__device__ float g_xs [BB*CC*LL];
__device__ float g_xs2[BB*CC*LL];
__device__ float g_s1d[CC];
__device__ float g_s2d[CC];
__device__ float g_s1f[CC];
__device__ float g_s2f[CC];

// ---------------- K1: q conv -> sigmoid gate -> x_atten -> q_ conv ----------------
__global__ void __launch_bounds__(256) k1_gate(const float* __restrict__ x,
                                               const float* __restrict__ qw,
                                               const float* __restrict__ kw) {
    __shared__ float qws[CPG*CPG], kws[CPG*CPG];
    int t = threadIdx.x;
    int g = blockIdx.y;
    if (blockIdx.x == 0 && g == 0 && t < CC) {
        g_s1d[t] = 0.f; g_s2d[t] = 0.f; g_s1f[t] = 0.f; g_s2f[t] = 0.f;
    }
    if (t < CPG*CPG) {
        qws[t] = qw[(size_t)g*CPG*CPG + t];
        kws[t] = kw[(size_t)g*CPG*CPG + t];
    }
    __syncthreads();
    int gl = blockIdx.x * 256 + t;
    int b = gl >> 11, l = gl & (LL-1);
    size_t base = (size_t)b*CC*LL + l + (size_t)g*CPG*LL;
    float xv[CPG], xa[CPG];
    #pragma unroll
    for (int i = 0; i < CPG; i++) xv[i] = x[base + (size_t)i*LL];
    #pragma unroll
    for (int c = 0; c < CPG; c++) {
        float s = 0.f;
        #pragma unroll
        for (int i = 0; i < CPG; i++) s = fmaf(qws[c*CPG+i], xv[i], s);
        xa[c] = xv[c] / (1.f + __expf(-s));
    }
    #pragma unroll
    for (int i = 0; i < CPG; i++) g_xat[base + (size_t)i*LL] = xa[i];
    #pragma unroll
    for (int c = 0; c < CPG; c++) {
        float s = 0.f;
        #pragma unroll
        for (int i = 0; i < CPG; i++) s = fmaf(kws[c*CPG+i], xa[i], s);
        g_qp[base + (size_t)c*LL] = s;
    }
}

// ---------------- K2: odd/even shuffle + down conv + BN stats (wide grid) ----------------
#define TM2 16
__global__ void __launch_bounds__(256) k2_down(const float* __restrict__ dw) {
    __shared__ float xt[CC][2*TM2 + 4];   // W = 36
    int t = threadIdx.x;
    int m0 = blockIdx.x * TM2, b = blockIdx.y;
    int l0 = 2*m0 - 2;
    const int W = 2*TM2 + 4;
    for (int idx = t; idx < CC*W; idx += 256) {
        int i = idx / W, s = idx % W;
        int l = l0 + s;
        xt[i][s] = (l >= 0 && l < LL) ? g_xat[((size_t)b*CC + i)*LL + l] : 0.f;
    }
    __syncthreads();
    int o = t >> 2, qq = t & 3;          // o: out channel, qq: 4 m's each
    float acc[4];
    #pragma unroll
    for (int j = 0; j < 4; j++) acc[j] = 0.f;
    const float* wb = dw + (size_t)o*CC*3;
    int sb = 2*(qq*4) + ((o < 32) ? 1 : 0);
    for (int i = 0; i < CC; i++) {
        float w0 = __ldg(wb + i*3 + 0), w1 = __ldg(wb + i*3 + 1), w2 = __ldg(wb + i*3 + 2);
        const float* row = xt[i];
        float a0 = row[sb], a1 = row[sb+2];
        #pragma unroll
        for (int j = 0; j < 4; j++) {
            float a2 = row[sb + 4 + 2*j];
            acc[j] = fmaf(w0, a0, fmaf(w1, a1, fmaf(w2, a2, acc[j])));
            a0 = a1; a1 = a2;
        }
    }
    float s1 = 0.f, s2 = 0.f;
    size_t base = ((size_t)b*CC + o)*MM + m0 + qq*4;
    #pragma unroll
    for (int j = 0; j < 4; j++) { float v = acc[j]; g_xa[base + j] = v; s1 += v; s2 = fmaf(v, v, s2); }
    s1 += __shfl_xor_sync(0xffffffffu, s1, 1); s2 += __shfl_xor_sync(0xffffffffu, s2, 1);
    s1 += __shfl_xor_sync(0xffffffffu, s1, 2); s2 += __shfl_xor_sync(0xffffffffu, s2, 2);
    if (qq == 0) { atomicAdd(&g_s1d[o], s1); atomicAdd(&g_s2d[o], s2); }
}

// ---------------- K3: BN + ReLU + v/v1 pointwise grouped convs ----------------
__global__ void __launch_bounds__(256) k3_vconv(const float* __restrict__ vw,
                                                const float* __restrict__ v1w,
                                                const float* __restrict__ dgam,
                                                const float* __restrict__ dbet) {
    __shared__ float sc[CPG], sh[CPG], vws[CPG*CPG], v1ws[CPG*CPG];
    int t = threadIdx.x;
    int g = blockIdx.y;
    if (t < CPG) {
        int c = g*CPG + t;
        const float invn = 1.f / (float)(BB*MM);
        float mean = g_s1d[c] * invn;
        float var  = g_s2d[c] * invn - mean*mean;
        float s = dgam[c] * rsqrtf(var + EPSV);
        sc[t] = s; sh[t] = dbet[c] - mean*s;
    }
    if (t < CPG*CPG) {
        vws[t]  = vw [(size_t)g*CPG*CPG + t];
        v1ws[t] = v1w[(size_t)g*CPG*CPG + t];
    }
    __syncthreads();
    int gl = blockIdx.x * 256 + t;
    int b = gl >> 10, m = gl & (MM-1);
    size_t base = (size_t)b*CC*MM + m + (size_t)g*CPG*MM;
    float xr[CPG];
    #pragma unroll
    for (int i = 0; i < CPG; i++)
        xr[i] = fmaxf(0.f, fmaf(g_xa[base + (size_t)i*MM], sc[i], sh[i]));
    #pragma unroll
    for (int c = 0; c < CPG; c++) {
        float s = 0.f, s1 = 0.f;
        #pragma unroll
        for (int i = 0; i < CPG; i++) {
            s  = fmaf(vws [c*CPG+i], xr[i], s);
            s1 = fmaf(v1ws[c*CPG+i], xr[i], s1);
        }
        g_v [base + (size_t)c*MM] = s;
        g_v1[base + (size_t)c*MM] = s1;
    }
}

// ---------------- K4: mma.sync tf32 flash attention (R14 best config) ----------------
#define NCH (MM/8)        // 128 chunks
#define K4M_SMEM (2*NCH*32*8 + 64)   // 65536 + colsum

__global__ void __launch_bounds__(512, 3) k4_mma() {
    extern __shared__ float2 sm4[];
    float2* KB = sm4;                      // [NCH*32]
    float2* VB = sm4 + NCH*32;             // [NCH*32]
    float* scv = (float*)(sm4 + 2*NCH*32); // [8] V column sums
    int t = threadIdx.x;
    int bh = blockIdx.y;
    size_t vb = (size_t)bh * EE * MM;      // b*CC + h*8 == 8*bh
    const float SCL = 0.35355339059327373f * 1.4426950408889634f;  // 1/sqrt(E)*log2(e)

    for (int i = t; i < NCH*32; i += 512) {
        int lane = i & 31, chunk = i >> 5;
        int j = lane & 3, g = lane >> 2;
        int m = chunk*8 + g;
        float k0 = g_v[vb + (size_t)(2*j  )*MM + m] * SCL;
        float k1 = g_v[vb + (size_t)(2*j+1)*MM + m] * SCL;
        float2 kk; kk.x = __uint_as_float(tf32r(k0)); kk.y = __uint_as_float(tf32r(k1));
        KB[i] = kk;
        float2 vv = *(const float2*)(g_v1 + vb + (size_t)g*MM + chunk*8 + 2*j);
        float2 vt; vt.x = __uint_as_float(tf32r(vv.x)); vt.y = __uint_as_float(tf32r(vv.y));
        VB[i] = vt;
    }
    // V column sums (exact fp32): warps 0..7 sum row (wid)
    {
        int lane = t & 31, wid = t >> 5;
        if (wid < EE) {
            float s = 0.f;
            const float* vr = g_v1 + vb + (size_t)wid*MM;
            for (int m = lane; m < MM; m += 32) s += vr[m];
            #pragma unroll
            for (int o = 16; o; o >>= 1) s += __shfl_xor_sync(0xffffffffu, s, o);
            if (lane == 0) scv[wid] = s;
        }
    }
    __syncthreads();

    int lane = t & 31, wid = t >> 5;
    int j = lane & 3, g = lane >> 2;
    int lr = blockIdx.x*512 + wid*32 + g;   // fragment A rows: lr, lr+8; B: lr+16, lr+24
    size_t qbase = (size_t)(8*bh)*LL;

    size_t q0 = qbase + (size_t)(2*j)*LL + lr;
    size_t q1 = qbase + (size_t)(2*j+1)*LL + lr;
    uint32_t qa0 = tf32r(g_qp[q0]),      qa1 = tf32r(g_qp[q1]);
    uint32_t qa2 = tf32r(g_qp[q0 + 8]),  qa3 = tf32r(g_qp[q1 + 8]);
    uint32_t qb0 = tf32r(g_qp[q0 + 16]), qb1 = tf32r(g_qp[q1 + 16]);
    uint32_t qb2 = tf32r(g_qp[q0 + 24]), qb3 = tf32r(g_qp[q1 + 24]);

    float dA0 = 0.f, dA1 = 0.f, dA2 = 0.f, dA3 = 0.f;
    float dB0 = 0.f, dB1 = 0.f, dB2 = 0.f, dB3 = 0.f;
    float denA0 = 0.f, denA1 = 0.f, denB0 = 0.f, denB1 = 0.f;
    const float2* kb = KB + lane;
    const float2* vp = VB + lane;
    const float zf = 0.f;

    #pragma unroll 2
    for (int c = 0; c < NCH; c++) {
        float2 kk = kb[c*32];
        float2 vv = vp[c*32];
        uint32_t bk0 = __float_as_uint(kk.x), bk1 = __float_as_uint(kk.y);
        float sA0, sA1, sA2, sA3, sB0, sB1, sB2, sB3;
        mma8(sA0, sA1, sA2, sA3, qa0, qa1, qa2, qa3, bk0, bk1, zf, zf, zf, zf);
        mma8(sB0, sB1, sB2, sB3, qb0, qb1, qb2, qb3, bk0, bk1, zf, zf, zf, zf);
        float pA0 = ex2f(sA0) - 1.f;
        float pA1 = ex2f(sA1) - 1.f;
        float pA2 = ex2f(sA2) - 1.f;
        float pA3 = ex2f(sA3) - 1.f;
        float pB0 = ex2f(sB0) - 1.f;
        float pB1 = ex2f(sB1) - 1.f;
        float pB2 = ex2f(sB2) - 1.f;
        float pB3 = ex2f(sB3) - 1.f;
        denA0 += pA0 + pA1; denA1 += pA2 + pA3;
        denB0 += pB0 + pB1; denB1 += pB2 + pB3;
        uint32_t bv0 = __float_as_uint(vv.x), bv1 = __float_as_uint(vv.y);
        mma8acc(dA0, dA1, dA2, dA3,
                __float_as_uint(pA0), __float_as_uint(pA1),
                __float_as_uint(pA2), __float_as_uint(pA3), bv0, bv1);
        mma8acc(dB0, dB1, dB2, dB3,
                __float_as_uint(pB0), __float_as_uint(pB1),
                __float_as_uint(pB2), __float_as_uint(pB3), bv0, bv1);
    }

    // reduce denominators across the 4-thread quad
    denA0 += __shfl_xor_sync(0xffffffffu, denA0, 1);
    denA0 += __shfl_xor_sync(0xffffffffu, denA0, 2);
    denA1 += __shfl_xor_sync(0xffffffffu, denA1, 1);
    denA1 += __shfl_xor_sync(0xffffffffu, denA1, 2);
    denB0 += __shfl_xor_sync(0xffffffffu, denB0, 1);
    denB0 += __shfl_xor_sync(0xffffffffu, denB0, 2);
    denB1 += __shfl_xor_sync(0xffffffffu, denB1, 1);
    denB1 += __shfl_xor_sync(0xffffffffu, denB1, 2);
    float iA0 = 1.f / ((float)MM + denA0);
    float iA1 = 1.f / ((float)MM + denA1);
    float iB0 = 1.f / ((float)MM + denB0);
    float iB1 = 1.f / ((float)MM + denB1);

    float cs0 = scv[2*j], cs1 = scv[2*j+1];
    size_t iA = qbase + (size_t)(2*j)*LL + lr;
    size_t iB = iA + LL;
    float o;
    o = (cs0 + dA0)*iA0; g_out[iA     ] = o; g_xs[iA     ] = o + g_xat[iA     ];
    o = (cs1 + dA1)*iA0; g_out[iB     ] = o; g_xs[iB     ] = o + g_xat[iB     ];
    o = (cs0 + dA2)*iA1; g_out[iA +  8] = o; g_xs[iA +  8] = o + g_xat[iA +  8];
    o = (cs1 + dA3)*iA1; g_out[iB +  8] = o; g_xs[iB +  8] = o + g_xat[iB +  8];
    o = (cs0 + dB0)*iB0; g_out[iA + 16] = o; g_xs[iA + 16] = o + g_xat[iA + 16];
    o = (cs1 + dB1)*iB0; g_out[iB + 16] = o; g_xs[iB + 16] = o + g_xat[iB + 16];
    o = (cs0 + dB2)*iB1; g_out[iA + 24] = o; g_xs[iA + 24] = o + g_xat[iA + 24];
    o = (cs1 + dB3)*iB1; g_out[iB + 24] = o; g_xs[iB + 24] = o + g_xat[iB + 24];
}

// ---------------- K5: out conv (K=3, groups=4) + residual + stats (wide grid) ----------------
#define TL5 64
__global__ void __launch_bounds__(256) k5_outconv(const float* __restrict__ ow) {
    __shared__ float xcs[48][TL5 + 2];
    int t = threadIdx.x;
    int l0 = blockIdx.x * TL5, g = blockIdx.y, b = blockIdx.z;
    const int W = TL5 + 2;   // 66
    for (int idx = t; idx < 48*W; idx += 256) {
        int j = idx / W, s = idx % W;
        int l = l0 - 1 + s;
        int u = g*48 + j;
        float val = 0.f;
        if (l >= 0 && l < LL) {
            const float* src; int ch;
            if      (u < 64)  { src = g_xs;  ch = u; }
            else if (u < 128) { src = g_qp;  ch = u - 64; }
            else              { src = g_out; ch = u - 128; }
            val = src[((size_t)b*CC + ch)*LL + l];
        }
        xcs[j][s] = val;
    }
    __syncthreads();
    int cl = t >> 4, sub = t & 15;
    int c = g*CPG + cl;
    int lbase = sub * 4;
    float acc[4];
    #pragma unroll
    for (int jj = 0; jj < 4; jj++) acc[jj] = 0.f;
    const float* wb = ow + (size_t)c*48*3;
    for (int j = 0; j < 48; j++) {
        float w0 = __ldg(wb + j*3 + 0), w1 = __ldg(wb + j*3 + 1), w2 = __ldg(wb + j*3 + 2);
        const float* row = xcs[j];
        float a0 = row[lbase], a1 = row[lbase+1];
        #pragma unroll
        for (int jj = 0; jj < 4; jj++) {
            float a2 = row[lbase + 2 + jj];
            acc[jj] = fmaf(w0, a0, fmaf(w1, a1, fmaf(w2, a2, acc[jj])));
            a0 = a1; a1 = a2;
        }
    }
    float s1 = 0.f, s2 = 0.f;
    size_t base = ((size_t)b*CC + c)*LL + l0 + lbase;
    #pragma unroll
    for (int jj = 0; jj < 4; jj++) {
        float v = acc[jj] + g_xs[base + jj];
        g_xs2[base + jj] = v;
        s1 += v; s2 = fmaf(v, v, s2);
    }
    #pragma unroll
    for (int k = 1; k < 16; k <<= 1) {
        s1 += __shfl_xor_sync(0xffffffffu, s1, k);
        s2 += __shfl_xor_sync(0xffffffffu, s2, k);
    }
    if (sub == 0) { atomicAdd(&g_s1f[c], s1); atomicAdd(&g_s2f[c], s2); }
}

// ---------------- K6: final BN + ReLU -> output ----------------
__global__ void __launch_bounds__(256) k6_final(const float* __restrict__ gam,
                                                const float* __restrict__ bet,
                                                float* __restrict__ out) {
    int idx = blockIdx.x * 256 + threadIdx.x;
    int c = (idx >> 11) & (CC-1);
    const float invn = 1.f / (float)(BB*LL);
    float mean = g_s1f[c] * invn;
    float var  = g_s2f[c] * invn - mean*mean;
    float s  = gam[c] * rsqrtf(var + EPSV);
    float shv = bet[c] - mean*s;
    out[idx] = fmaxf(0.f, fmaf(g_xs2[idx], s, shv));
}

// ---------------- launch ----------------
extern "C" void kernel_launch(void* const* d_in, const int* in_sizes, int n_in,
                              void* d_out, int out_size) {
    const float* x   = (const float*)d_in[0];
    const float* qw  = (const float*)d_in[1];
    const float* kw  = (const float*)d_in[2];
    const float* vw  = (const float*)d_in[3];
    const float* v1w = (const float*)d_in[4];
    const float* ow  = (const float*)d_in[5];
    const float* dw  = (const float*)d_in[6];
    const float* dg  = (const float*)d_in[7];
    const float* db  = (const float*)d_in[8];
    const float* gam = (const float*)d_in[9];
    const float* bet = (const float*)d_in[10];
    float* out = (float*)d_out;

    static int configured = 0;
    if (!configured) {
        cudaFuncSetAttribute(k4_mma, cudaFuncAttributeMaxDynamicSharedMemorySize, K4M_SMEM);
        configured = 1;
    }

    k1_gate<<<dim3((BB*LL)/256, GG), 256>>>(x, qw, kw);
    k2_down<<<dim3(MM/TM2, BB), 256>>>(dw);
    k3_vconv<<<dim3((BB*MM)/256, GG), 256>>>(vw, v1w, dg, db);
    k4_mma<<<dim3(LL/512, BB*HH), 512, K4M_SMEM>>>();
    k5_outconv<<<dim3(LL/TL5, GG, BB), 256>>>(ow);
    k6_final<<<(BB*CC*LL)/256, 256>>>(gam, bet, out);
}